// round 13
// baseline (speedup 1.0000x reference)
#include <cuda_runtime.h>
#include <math.h>

#define NCTA 128
#define TPB  256
#define RPB  4          // batch rows per CTA: 128*4 = 512
#define BSZ  512
#define LAT  256
#define HID  512
#define TST  8

typedef unsigned long long ull;

// ---------------- device scratch --------------------------------------------
__device__ float  g_traj[BSZ * TST * LAT];
__device__ double g_part[2][NCTA];
__device__ unsigned g_bar_gen = 0;
__device__ unsigned g_bar_cnt = 0;

// ---------------- Dormand-Prince tableau ------------------------------------
__constant__ float c_C[7] = {0.0f, 0.2f, 0.3f, 0.8f, (float)(8.0/9.0), 1.0f, 1.0f};
__constant__ float c_A[7][6] = {
  {0,0,0,0,0,0},
  {0.2f,0,0,0,0,0},
  {(float)(3.0/40.0),(float)(9.0/40.0),0,0,0,0},
  {(float)(44.0/45.0),(float)(-56.0/15.0),(float)(32.0/9.0),0,0,0},
  {(float)(19372.0/6561.0),(float)(-25360.0/2187.0),(float)(64448.0/6561.0),(float)(-212.0/729.0),0,0},
  {(float)(9017.0/3168.0),(float)(-355.0/33.0),(float)(46732.0/5247.0),(float)(49.0/176.0),(float)(-5103.0/18656.0),0},
  {(float)(35.0/384.0),0.0f,(float)(500.0/1113.0),(float)(125.0/192.0),(float)(-2187.0/6784.0),(float)(11.0/84.0)}
};
__constant__ float c_B5[7] = {
  (float)(35.0/384.0), 0.0f, (float)(500.0/1113.0), (float)(125.0/192.0),
  (float)(-2187.0/6784.0), (float)(11.0/84.0), 0.0f};
__constant__ float c_D[7] = {
  (float)(35.0/384.0 - 5179.0/57600.0), 0.0f,
  (float)(500.0/1113.0 - 7571.0/16695.0),
  (float)(125.0/192.0 - 393.0/640.0),
  (float)(-2187.0/6784.0 + 92097.0/339200.0),
  (float)(11.0/84.0 - 187.0/2100.0),
  (float)(-1.0/40.0)};

// ---------------- shared memory layout --------------------------------------
// Activations stored DUPLICATED: element (r,c) is float2{v,v}; LDS.128 yields
// two ready-made f32x2 splat operands for fma.rn.f32x2 (broadcast, no conflicts).
struct __align__(16) Smem {
  float  z [RPB][LAT];            // 4 KB
  float  k [7][RPB][LAT];         // 28 KB
  float2 a [RPB][264];            // 8.25 KB
  float2 h1[RPB][520];            // 16.25 KB
  float2 h2[RPB][520];            // 16.25 KB
  ulonglong2 sc[2048];            // 32 KB split-K partial pairs (both layouts)
  double red[TPB];                // 2 KB
};
#define SMEM_BYTES ((int)sizeof(Smem))

// ---------------- packed fp32 FMA (sm_103a FFMA2) ---------------------------
__device__ __forceinline__ void ffma2(ull& d, ull a, ull b) {
  asm("fma.rn.f32x2 %0, %1, %2, %0;" : "+l"(d) : "l"(a), "l"(b));
}
__device__ __forceinline__ float plo(ull v) { return __uint_as_float((unsigned)v); }
__device__ __forceinline__ float phi(ull v) { return __uint_as_float((unsigned)(v >> 32)); }

// ---------------- manual grid barrier ----------------------------------------
__device__ __forceinline__ void grid_sync() {
  __syncthreads();
  if (threadIdx.x == 0) {
    __threadfence();
    unsigned gen = *(volatile unsigned*)&g_bar_gen;
    unsigned arrived = atomicAdd(&g_bar_cnt, 1u);
    if (arrived == NCTA - 1u) {
      atomicExch(&g_bar_cnt, 0u);
      __threadfence();
      atomicAdd(&g_bar_gen, 1u);
    } else {
      while (*(volatile unsigned*)&g_bar_gen == gen) { __nanosleep(64); }
    }
    __threadfence();
  }
  __syncthreads();
}

// ---------------- N=512 layer, CP=4 (8 cols/thread), split-K x4 --------------
// 64 col-threads (tid&63) each own 8 columns (4 f32x2 pairs); group q = tid>>6
// takes quarter q of K (group 3 absorbs the K=257 tail). All groups spill;
// all 256 threads combine (one (col-thread,row) item each).
template<bool RELU>
__device__ __forceinline__ void layer_n512(
    const float* __restrict__ W, const float* __restrict__ bias,
    const float2* __restrict__ inD, int inStride,
    float2* __restrict__ outD, int outStride,
    int K, int tid, ulonglong2* __restrict__ scratch)
{
  const int ct = tid & 63;
  const int q  = tid >> 6;
  const int n0 = ct * 8;
  const int Kq = K >> 2;
  const int kstart = q * Kq;
  const int kend   = (q == 3) ? K : kstart + Kq;

  ull acc[RPB][4];
  {
    ull b0 = 0, b1 = 0, b2 = 0, b3 = 0;
    if (q == 0) {
      ulonglong2 bv0 = *reinterpret_cast<const ulonglong2*>(bias + n0);
      ulonglong2 bv1 = *reinterpret_cast<const ulonglong2*>(bias + n0 + 4);
      b0 = bv0.x; b1 = bv0.y; b2 = bv1.x; b3 = bv1.y;
    }
    #pragma unroll
    for (int r = 0; r < RPB; r++) {
      acc[r][0] = b0; acc[r][1] = b1; acc[r][2] = b2; acc[r][3] = b3;
    }
  }

  int k = kstart;
  #pragma unroll 2
  for (; k + 4 <= kend; k += 4) {
    ull w[4][4];
    #pragma unroll
    for (int kk = 0; kk < 4; kk++) {
      const ulonglong2* wp =
          reinterpret_cast<const ulonglong2*>(W + (size_t)(k + kk) * 512 + n0);
      ulonglong2 wa = wp[0], wb = wp[1];
      w[kk][0] = wa.x; w[kk][1] = wa.y; w[kk][2] = wb.x; w[kk][3] = wb.y;
    }
    #pragma unroll
    for (int r = 0; r < RPB; r++) {
      const ulonglong2* ap =
          reinterpret_cast<const ulonglong2*>(inD + (size_t)r * inStride + k);
      ulonglong2 a01 = ap[0];
      ulonglong2 a23 = ap[1];
      #pragma unroll
      for (int c = 0; c < 4; c++) {
        ffma2(acc[r][c], a01.x, w[0][c]);
        ffma2(acc[r][c], a01.y, w[1][c]);
        ffma2(acc[r][c], a23.x, w[2][c]);
        ffma2(acc[r][c], a23.y, w[3][c]);
      }
    }
  }
  for (; k < kend; k++) {                  // tail (K=257: k=256, group 3 only)
    const ulonglong2* wp =
        reinterpret_cast<const ulonglong2*>(W + (size_t)k * 512 + n0);
    ulonglong2 wa = wp[0], wb = wp[1];
    #pragma unroll
    for (int r = 0; r < RPB; r++) {
      ull av = *reinterpret_cast<const ull*>(inD + (size_t)r * inStride + k);
      ffma2(acc[r][0], av, wa.x); ffma2(acc[r][1], av, wa.y);
      ffma2(acc[r][2], av, wb.x); ffma2(acc[r][3], av, wb.y);
    }
  }

  #pragma unroll
  for (int r = 0; r < RPB; r++) {
    int base = ((q * RPB + r) * 64 + ct) * 2;
    scratch[base    ] = make_ulonglong2(acc[r][0], acc[r][1]);
    scratch[base + 1] = make_ulonglong2(acc[r][2], acc[r][3]);
  }
  __syncthreads();

  // parallel combine: 256 threads, one (col-thread,row) item each
  {
    const int ct2 = tid & 63;
    const int r2  = tid >> 6;
    float v[8];
    #pragma unroll
    for (int i = 0; i < 8; i++) v[i] = 0.0f;
    #pragma unroll
    for (int qq = 0; qq < 4; qq++) {
      int base = ((qq * RPB + r2) * 64 + ct2) * 2;
      ulonglong2 p0 = scratch[base], p1 = scratch[base + 1];
      v[0] += plo(p0.x); v[1] += phi(p0.x);
      v[2] += plo(p0.y); v[3] += phi(p0.y);
      v[4] += plo(p1.x); v[5] += phi(p1.x);
      v[6] += plo(p1.y); v[7] += phi(p1.y);
    }
    if (RELU) {
      #pragma unroll
      for (int i = 0; i < 8; i++) v[i] = fmaxf(v[i], 0.0f);
    }
    float4* o4 = reinterpret_cast<float4*>(outD + (size_t)r2 * outStride + ct2 * 8);
    o4[0] = make_float4(v[0], v[0], v[1], v[1]);
    o4[1] = make_float4(v[2], v[2], v[3], v[3]);
    o4[2] = make_float4(v[4], v[4], v[5], v[5]);
    o4[3] = make_float4(v[6], v[6], v[7], v[7]);
  }
  __syncthreads();
}

// ---------------- N=256 layer, CP=4, split-K x8 -------------------------------
// 32 col-threads (tid&31) own 8 columns each; group q = tid>>5 takes eighth q
// of K (K=512 at both call sites). Combine on 128 threads.
template<bool RELU, bool DUPOUT>
__device__ __forceinline__ void layer_n256(
    const float* __restrict__ W, const float* __restrict__ bias,
    const float2* __restrict__ inD, int inStride,
    float2* __restrict__ outD, float* __restrict__ outS, int outStride,
    int K, int tid, ulonglong2* __restrict__ scratch)
{
  const int ct = tid & 31;
  const int q  = tid >> 5;
  const int n0 = ct * 8;
  const int Kq = K >> 3;
  const int kstart = q * Kq;
  const int kend   = kstart + Kq;

  ull acc[RPB][4];
  {
    ull b0 = 0, b1 = 0, b2 = 0, b3 = 0;
    if (q == 0) {
      ulonglong2 bv0 = *reinterpret_cast<const ulonglong2*>(bias + n0);
      ulonglong2 bv1 = *reinterpret_cast<const ulonglong2*>(bias + n0 + 4);
      b0 = bv0.x; b1 = bv0.y; b2 = bv1.x; b3 = bv1.y;
    }
    #pragma unroll
    for (int r = 0; r < RPB; r++) {
      acc[r][0] = b0; acc[r][1] = b1; acc[r][2] = b2; acc[r][3] = b3;
    }
  }

  int k = kstart;
  #pragma unroll 2
  for (; k + 4 <= kend; k += 4) {
    ull w[4][4];
    #pragma unroll
    for (int kk = 0; kk < 4; kk++) {
      const ulonglong2* wp =
          reinterpret_cast<const ulonglong2*>(W + (size_t)(k + kk) * 256 + n0);
      ulonglong2 wa = wp[0], wb = wp[1];
      w[kk][0] = wa.x; w[kk][1] = wa.y; w[kk][2] = wb.x; w[kk][3] = wb.y;
    }
    #pragma unroll
    for (int r = 0; r < RPB; r++) {
      const ulonglong2* ap =
          reinterpret_cast<const ulonglong2*>(inD + (size_t)r * inStride + k);
      ulonglong2 a01 = ap[0];
      ulonglong2 a23 = ap[1];
      #pragma unroll
      for (int c = 0; c < 4; c++) {
        ffma2(acc[r][c], a01.x, w[0][c]);
        ffma2(acc[r][c], a01.y, w[1][c]);
        ffma2(acc[r][c], a23.x, w[2][c]);
        ffma2(acc[r][c], a23.y, w[3][c]);
      }
    }
  }

  #pragma unroll
  for (int r = 0; r < RPB; r++) {
    int base = ((q * RPB + r) * 32 + ct) * 2;
    scratch[base    ] = make_ulonglong2(acc[r][0], acc[r][1]);
    scratch[base + 1] = make_ulonglong2(acc[r][2], acc[r][3]);
  }
  __syncthreads();

  if (tid < 128) {                         // combine: 128 items
    const int ct2 = tid & 31;
    const int r2  = tid >> 5;
    float v[8];
    #pragma unroll
    for (int i = 0; i < 8; i++) v[i] = 0.0f;
    #pragma unroll
    for (int qq = 0; qq < 8; qq++) {
      int base = ((qq * RPB + r2) * 32 + ct2) * 2;
      ulonglong2 p0 = scratch[base], p1 = scratch[base + 1];
      v[0] += plo(p0.x); v[1] += phi(p0.x);
      v[2] += plo(p0.y); v[3] += phi(p0.y);
      v[4] += plo(p1.x); v[5] += phi(p1.x);
      v[6] += plo(p1.y); v[7] += phi(p1.y);
    }
    if (RELU) {
      #pragma unroll
      for (int i = 0; i < 8; i++) v[i] = fmaxf(v[i], 0.0f);
    }
    if constexpr (DUPOUT) {
      float4* o4 = reinterpret_cast<float4*>(outD + (size_t)r2 * outStride + ct2 * 8);
      o4[0] = make_float4(v[0], v[0], v[1], v[1]);
      o4[1] = make_float4(v[2], v[2], v[3], v[3]);
      o4[2] = make_float4(v[4], v[4], v[5], v[5]);
      o4[3] = make_float4(v[6], v[6], v[7], v[7]);
    } else {
      float4* o4 = reinterpret_cast<float4*>(outS + (size_t)r2 * outStride + ct2 * 8);
      o4[0] = make_float4(v[0], v[1], v[2], v[3]);
      o4[1] = make_float4(v[4], v[5], v[6], v[7]);
    }
  }
  __syncthreads();
}

// ---------------- persistent kernel ------------------------------------------
__global__ void __launch_bounds__(TPB, 1) ode_kernel(
    const float* __restrict__ z0,  const float* __restrict__ ts,
    const float* __restrict__ W1,  const float* __restrict__ b1,
    const float* __restrict__ W2,  const float* __restrict__ b2,
    const float* __restrict__ W3,  const float* __restrict__ b3,
    const float* __restrict__ W4,  const float* __restrict__ b4,
    const float* __restrict__ P1,  const float* __restrict__ pb1,
    const float* __restrict__ P2,  const float* __restrict__ pb2,
    const float* __restrict__ P3,  const float* __restrict__ pb3,
    const float* __restrict__ P4,  const float* __restrict__ pb4,
    float* __restrict__ out)
{
  extern __shared__ char smem_raw[];
  Smem* S = reinterpret_cast<Smem*>(smem_raw);
  const int tid  = threadIdx.x;
  const int row0 = blockIdx.x * RPB;

  for (int e = tid; e < RPB * LAT; e += TPB) {
    int r = e >> 8, c = e & 255;
    float v = z0[(row0 + r) * LAT + c];
    S->z[r][c] = v;
    g_traj[((row0 + r) * TST + 0) * LAT + c] = v;
  }
  __syncthreads();

  float dt = (ts[1] - ts[0]) * 0.1f;
  int pbuf = 0;

  for (int seg = 0; seg < TST - 1; seg++) {
    const float t1v = ts[seg + 1];
    float t = ts[seg];

    for (int step = 0; step < 12; step++) {
      float remaining = t1v - t;
      if (!(remaining > 1e-10f)) break;
      float dt_try = fminf(dt, remaining);

      // ---- 7 RK stages ----
      for (int i = 0; i < 7; i++) {
        float ti = t + c_C[i] * dt_try;
        for (int e = tid; e < RPB * LAT; e += TPB) {
          int r = e >> 8, c = e & 255;
          float v = S->z[r][c];
          #pragma unroll
          for (int j = 0; j < 6; j++) {
            if (j < i) {
              float aij = c_A[i][j];
              if (aij != 0.0f) v += (dt_try * aij) * S->k[j][r][c];
            }
          }
          S->a[r][c] = make_float2(v, v);
        }
        if (tid < RPB) S->a[tid][256] = make_float2(ti, ti);
        __syncthreads();

        layer_n512<true>(W1, b1, &S->a [0][0], 264, &S->h1[0][0], 520, LAT + 1, tid, S->sc);
        layer_n512<true>(W2, b2, &S->h1[0][0], 520, &S->h2[0][0], 520, HID,     tid, S->sc);
        layer_n512<true>(W3, b3, &S->h2[0][0], 520, &S->h1[0][0], 520, HID,     tid, S->sc);
        layer_n256<false, false>(W4, b4, &S->h1[0][0], 520,
                                 nullptr, &S->k[i][0][0], LAT, HID, tid, S->sc);
      }

      // ---- z5, err, local partial ----
      double part = 0.0;
      for (int e = tid; e < RPB * LAT; e += TPB) {
        int r = e >> 8, c = e & 255;
        float zo = S->z[r][c];
        float z5 = zo, err = 0.0f;
        #pragma unroll
        for (int i = 0; i < 7; i++) {
          float ki = S->k[i][r][c];
          float b5 = c_B5[i];
          if (b5 != 0.0f) z5 += (dt_try * b5) * ki;
          float d = c_D[i];
          if (d != 0.0f) err += (dt_try * d) * ki;
        }
        S->a[r][c] = make_float2(z5, z5);
        float sc = 1e-4f + 1e-3f * fmaxf(fabsf(zo), fabsf(z5));
        float ra = err / sc;
        part += (double)(ra * ra);
      }
      S->red[tid] = part;
      __syncthreads();
      for (int s = TPB / 2; s > 0; s >>= 1) {
        if (tid < s) S->red[tid] += S->red[tid + s];
        __syncthreads();
      }
      if (tid == 0) g_part[pbuf][blockIdx.x] = S->red[0];

      grid_sync();                         // ONE grid barrier per step

      double ssum = 0.0;
      for (int j = 0; j < NCTA; j++) ssum += g_part[pbuf][j];
      float en = sqrtf((float)(ssum / (double)(BSZ * LAT)));
      bool accept  = (en <= 1.0f);
      float factor = fminf(fmaxf(0.9f * powf(fmaxf(en, 1e-9f), -0.2f), 0.2f), 10.0f);

      if (accept) {
        for (int e = tid; e < RPB * LAT; e += TPB) {
          int r = e >> 8, c = e & 255;
          S->z[r][c] = S->a[r][c].x;
        }
        t = t + dt_try;
      }
      dt = dt_try * factor;
      pbuf ^= 1;
      __syncthreads();
    }

    for (int e = tid; e < RPB * LAT; e += TPB) {
      int r = e >> 8, c = e & 255;
      g_traj[((row0 + r) * TST + (seg + 1)) * LAT + c] = S->z[r][c];
    }
    __syncthreads();
  }

  // ---- pose head (runs once; small share of total) ----
  for (int tix = 0; tix < TST; tix++) {
    for (int e = tid; e < RPB * LAT; e += TPB) {
      int r = e >> 8, c = e & 255;
      float v = g_traj[((row0 + r) * TST + tix) * LAT + c];
      S->a[r][c] = make_float2(v, v);
    }
    __syncthreads();

    layer_n512<true>(P1, pb1, &S->a[0][0], 264, &S->h1[0][0], 520, LAT, tid, S->sc);
    layer_n256<true, true>(P2, pb2, &S->h1[0][0], 520,
                           &S->h2[0][0], nullptr, 520, 512, tid, S->sc);

    // P3: 256 -> 128 (tiny), 128 threads, all rows
    if (tid < 128) {
      float acc[RPB];
      #pragma unroll
      for (int r = 0; r < RPB; r++) acc[r] = pb3[tid];
      #pragma unroll 4
      for (int k = 0; k < 256; k++) {
        float wv = P3[k * 128 + tid];
        #pragma unroll
        for (int r = 0; r < RPB; r++)
          acc[r] = fmaf(S->h2[r][k].x, wv, acc[r]);
      }
      #pragma unroll
      for (int r = 0; r < RPB; r++) {
        float v = fmaxf(acc[r], 0.0f);
        S->h1[r][tid] = make_float2(v, v);
      }
    }
    __syncthreads();

    if (tid < RPB * 7) {                   // final 128 -> 7
      int r = tid / 7, c = tid % 7;
      float acc = pb4[c];
      #pragma unroll 4
      for (int kk = 0; kk < 128; kk++)
        acc = fmaf(S->h1[r][kk].x, P4[kk * 7 + c], acc);
      S->z[r][c] = acc;
    }
    __syncthreads();

    if (tid < RPB) {
      int r = tid;
      float q0 = S->z[r][3], q1 = S->z[r][4], q2 = S->z[r][5], q3 = S->z[r][6];
      float nrm = sqrtf(q0*q0 + q1*q1 + q2*q2 + q3*q3);
      float dn  = fmaxf(nrm, 1e-12f);
      float* o = out + ((size_t)(row0 + r) * TST + tix) * 7;
      o[0] = S->z[r][0]; o[1] = S->z[r][1]; o[2] = S->z[r][2];
      o[3] = q0 / dn; o[4] = q1 / dn; o[5] = q2 / dn; o[6] = q3 / dn;
    }
    __syncthreads();
  }
}

// ---------------- launch ------------------------------------------------------
extern "C" void kernel_launch(void* const* d_in, const int* in_sizes, int n_in,
                              void* d_out, int out_size) {
  (void)in_sizes; (void)n_in; (void)out_size;
  const float* z0  = (const float*)d_in[0];
  const float* ts  = (const float*)d_in[1];
  const float* W1  = (const float*)d_in[2];
  const float* b1  = (const float*)d_in[3];
  const float* W2  = (const float*)d_in[4];
  const float* b2  = (const float*)d_in[5];
  const float* W3  = (const float*)d_in[6];
  const float* b3  = (const float*)d_in[7];
  const float* W4  = (const float*)d_in[8];
  const float* b4  = (const float*)d_in[9];
  const float* P1  = (const float*)d_in[10];
  const float* pb1 = (const float*)d_in[11];
  const float* P2  = (const float*)d_in[12];
  const float* pb2 = (const float*)d_in[13];
  const float* P3  = (const float*)d_in[14];
  const float* pb3 = (const float*)d_in[15];
  const float* P4  = (const float*)d_in[16];
  const float* pb4 = (const float*)d_in[17];
  float* out = (float*)d_out;

  cudaFuncSetAttribute(ode_kernel, cudaFuncAttributeMaxDynamicSharedMemorySize,
                       SMEM_BYTES);
  ode_kernel<<<NCTA, TPB, SMEM_BYTES>>>(z0, ts, W1, b1, W2, b2, W3, b3, W4, b4,
                                        P1, pb1, P2, pb2, P3, pb3, P4, pb4, out);
}

// round 14
// speedup vs baseline: 1.0526x; 1.0526x over previous
#include <cuda_runtime.h>
#include <math.h>

#define NCTA 128
#define TPB  512
#define RPB  4          // batch rows per CTA: 128*4 = 512
#define BSZ  512
#define LAT  256
#define HID  512
#define TST  8

typedef unsigned long long ull;

// ---------------- device scratch --------------------------------------------
__device__ float  g_traj[BSZ * TST * LAT];
__device__ double g_part[2][NCTA];
__device__ unsigned g_bar_gen = 0;
__device__ unsigned g_bar_cnt = 0;

// ---------------- Dormand-Prince tableau ------------------------------------
__constant__ float c_C[7] = {0.0f, 0.2f, 0.3f, 0.8f, (float)(8.0/9.0), 1.0f, 1.0f};
__constant__ float c_A[7][6] = {
  {0,0,0,0,0,0},
  {0.2f,0,0,0,0,0},
  {(float)(3.0/40.0),(float)(9.0/40.0),0,0,0,0},
  {(float)(44.0/45.0),(float)(-56.0/15.0),(float)(32.0/9.0),0,0,0},
  {(float)(19372.0/6561.0),(float)(-25360.0/2187.0),(float)(64448.0/6561.0),(float)(-212.0/729.0),0,0},
  {(float)(9017.0/3168.0),(float)(-355.0/33.0),(float)(46732.0/5247.0),(float)(49.0/176.0),(float)(-5103.0/18656.0),0},
  {(float)(35.0/384.0),0.0f,(float)(500.0/1113.0),(float)(125.0/192.0),(float)(-2187.0/6784.0),(float)(11.0/84.0)}
};
__constant__ float c_B5[7] = {
  (float)(35.0/384.0), 0.0f, (float)(500.0/1113.0), (float)(125.0/192.0),
  (float)(-2187.0/6784.0), (float)(11.0/84.0), 0.0f};
__constant__ float c_D[7] = {
  (float)(35.0/384.0 - 5179.0/57600.0), 0.0f,
  (float)(500.0/1113.0 - 7571.0/16695.0),
  (float)(125.0/192.0 - 393.0/640.0),
  (float)(-2187.0/6784.0 + 92097.0/339200.0),
  (float)(11.0/84.0 - 187.0/2100.0),
  (float)(-1.0/40.0)};

// ---------------- shared memory layout --------------------------------------
// Activations stored DUPLICATED: element (r,c) is float2{v,v}; LDS.128 yields
// two ready-made f32x2 splat operands for fma.rn.f32x2 (broadcast, no conflicts).
struct __align__(16) Smem {
  float  z [RPB][LAT];            // 4 KB
  float  k [7][RPB][LAT];         // 28 KB
  float2 a [RPB][264];            // 8.25 KB
  float2 h1[RPB][520];            // 16.25 KB
  float2 h2[RPB][520];            // 16.25 KB
  ulonglong2 sc[4096];            // 64 KB split-K partial pairs (both layouts)
  double red[16];                 // warp partials
  float  bcast[2];                // accept flag, factor
};
#define SMEM_BYTES ((int)sizeof(Smem))

// ---------------- packed fp32 FMA (sm_103a FFMA2) ---------------------------
__device__ __forceinline__ void ffma2(ull& d, ull a, ull b) {
  asm("fma.rn.f32x2 %0, %1, %2, %0;" : "+l"(d) : "l"(a), "l"(b));
}
__device__ __forceinline__ float plo(ull v) { return __uint_as_float((unsigned)v); }
__device__ __forceinline__ float phi(ull v) { return __uint_as_float((unsigned)(v >> 32)); }

// ---------------- manual grid barrier ----------------------------------------
__device__ __forceinline__ void grid_sync() {
  __syncthreads();
  if (threadIdx.x == 0) {
    __threadfence();
    unsigned gen = *(volatile unsigned*)&g_bar_gen;
    unsigned arrived = atomicAdd(&g_bar_cnt, 1u);
    if (arrived == NCTA - 1u) {
      atomicExch(&g_bar_cnt, 0u);
      __threadfence();
      atomicAdd(&g_bar_gen, 1u);
    } else {
      while (*(volatile unsigned*)&g_bar_gen == gen) { __nanosleep(64); }
    }
    __threadfence();
  }
  __syncthreads();
}

// ---------------- N=512 layer, CP=4 (8 cols/thread), split-K x8 --------------
// 64 col-threads (tid&63) own 8 columns (4 f32x2 pairs); group q = tid>>6 takes
// eighth q of K (group 7 absorbs the K=257 tail). Inner loop stages only 2
// k-rows (16 regs) to stay under the 128-reg cap at TPB=512. All groups spill;
// 512 threads combine (one (ct,row,col-half) item each).
template<bool RELU>
__device__ __forceinline__ void layer_n512(
    const float* __restrict__ W, const float* __restrict__ bias,
    const float2* __restrict__ inD, int inStride,
    float2* __restrict__ outD, int outStride,
    int K, int tid, ulonglong2* __restrict__ scratch)
{
  const int ct = tid & 63;
  const int q  = tid >> 6;
  const int n0 = ct * 8;
  const int Kq = K >> 3;
  const int kstart = q * Kq;
  const int kend   = (q == 7) ? K : kstart + Kq;

  ull acc[RPB][4];
  {
    ull b0 = 0, b1 = 0, b2 = 0, b3 = 0;
    if (q == 0) {
      ulonglong2 bv0 = *reinterpret_cast<const ulonglong2*>(bias + n0);
      ulonglong2 bv1 = *reinterpret_cast<const ulonglong2*>(bias + n0 + 4);
      b0 = bv0.x; b1 = bv0.y; b2 = bv1.x; b3 = bv1.y;
    }
    #pragma unroll
    for (int r = 0; r < RPB; r++) {
      acc[r][0] = b0; acc[r][1] = b1; acc[r][2] = b2; acc[r][3] = b3;
    }
  }

  int k = kstart;
  #pragma unroll 2
  for (; k + 2 <= kend; k += 2) {
    // stage 2 k-rows x 8 cols = 64B = 16 regs
    const ulonglong2* wp0 =
        reinterpret_cast<const ulonglong2*>(W + (size_t)k * 512 + n0);
    const ulonglong2* wp1 =
        reinterpret_cast<const ulonglong2*>(W + (size_t)(k + 1) * 512 + n0);
    ulonglong2 w0a = wp0[0], w0b = wp0[1];
    ulonglong2 w1a = wp1[0], w1b = wp1[1];
    #pragma unroll
    for (int r = 0; r < RPB; r++) {
      ulonglong2 a01 = *reinterpret_cast<const ulonglong2*>(
          inD + (size_t)r * inStride + k);        // splat pairs for k, k+1
      ffma2(acc[r][0], a01.x, w0a.x);
      ffma2(acc[r][1], a01.x, w0a.y);
      ffma2(acc[r][2], a01.x, w0b.x);
      ffma2(acc[r][3], a01.x, w0b.y);
      ffma2(acc[r][0], a01.y, w1a.x);
      ffma2(acc[r][1], a01.y, w1a.y);
      ffma2(acc[r][2], a01.y, w1b.x);
      ffma2(acc[r][3], a01.y, w1b.y);
    }
  }
  for (; k < kend; k++) {                // tail (K=257: k=256, group 7 only)
    const ulonglong2* wp =
        reinterpret_cast<const ulonglong2*>(W + (size_t)k * 512 + n0);
    ulonglong2 wa = wp[0], wb = wp[1];
    #pragma unroll
    for (int r = 0; r < RPB; r++) {
      ull av = *reinterpret_cast<const ull*>(inD + (size_t)r * inStride + k);
      ffma2(acc[r][0], av, wa.x); ffma2(acc[r][1], av, wa.y);
      ffma2(acc[r][2], av, wb.x); ffma2(acc[r][3], av, wb.y);
    }
  }

  #pragma unroll
  for (int r = 0; r < RPB; r++) {
    int base = ((q * RPB + r) * 64 + ct) * 2;
    scratch[base    ] = make_ulonglong2(acc[r][0], acc[r][1]);
    scratch[base + 1] = make_ulonglong2(acc[r][2], acc[r][3]);
  }
  __syncthreads();

  // parallel combine: 512 threads = 64 ct x 4 rows x 2 col-halves
  {
    const int ct2 = tid & 63;
    const int r2  = (tid >> 6) & 3;
    const int h   = tid >> 8;            // which ulonglong2 slot (cols 0-3 / 4-7)
    float v0 = 0.0f, v1 = 0.0f, v2 = 0.0f, v3 = 0.0f;
    #pragma unroll
    for (int qq = 0; qq < 8; qq++) {
      ulonglong2 p = scratch[((qq * RPB + r2) * 64 + ct2) * 2 + h];
      v0 += plo(p.x); v1 += phi(p.x);
      v2 += plo(p.y); v3 += phi(p.y);
    }
    if (RELU) {
      v0 = fmaxf(v0, 0.0f); v1 = fmaxf(v1, 0.0f);
      v2 = fmaxf(v2, 0.0f); v3 = fmaxf(v3, 0.0f);
    }
    float4* o4 = reinterpret_cast<float4*>(outD + (size_t)r2 * outStride + ct2 * 8 + h * 4);
    o4[0] = make_float4(v0, v0, v1, v1);
    o4[1] = make_float4(v2, v2, v3, v3);
  }
  __syncthreads();
}

// ---------------- N=256 layer, CP=2, split-K x8 (R12, validated) -------------
// 64 col-threads (tid&63) own 4 columns each; group q = tid>>6 takes eighth q
// of K (K=512 at both call sites). Parallel combine on 256 threads.
template<bool RELU, bool DUPOUT>
__device__ __forceinline__ void layer_n256(
    const float* __restrict__ W, const float* __restrict__ bias,
    const float2* __restrict__ inD, int inStride,
    float2* __restrict__ outD, float* __restrict__ outS, int outStride,
    int K, int tid, ulonglong2* __restrict__ scratch)
{
  const int ct = tid & 63;
  const int q  = tid >> 6;
  const int n0 = ct * 4;
  const int Kq = K >> 3;
  const int kstart = q * Kq;
  const int kend   = kstart + Kq;

  ull acc0[RPB], acc1[RPB];
  ull b0 = 0, b1 = 0;
  if (q == 0) {
    ulonglong2 bv = *reinterpret_cast<const ulonglong2*>(bias + n0);
    b0 = bv.x; b1 = bv.y;
  }
  #pragma unroll
  for (int r = 0; r < RPB; r++) { acc0[r] = b0; acc1[r] = b1; }

  int k = kstart;
  #pragma unroll 2
  for (; k + 4 <= kend; k += 4) {
    const float* Wk = W + (size_t)k * 256 + n0;
    ulonglong2 w0 = *reinterpret_cast<const ulonglong2*>(Wk);
    ulonglong2 w1 = *reinterpret_cast<const ulonglong2*>(Wk + 256);
    ulonglong2 w2 = *reinterpret_cast<const ulonglong2*>(Wk + 512);
    ulonglong2 w3 = *reinterpret_cast<const ulonglong2*>(Wk + 768);
    #pragma unroll
    for (int r = 0; r < RPB; r++) {
      const ulonglong2* ap =
          reinterpret_cast<const ulonglong2*>(inD + (size_t)r * inStride + k);
      ulonglong2 a01 = ap[0];
      ulonglong2 a23 = ap[1];
      ffma2(acc0[r], a01.x, w0.x); ffma2(acc1[r], a01.x, w0.y);
      ffma2(acc0[r], a01.y, w1.x); ffma2(acc1[r], a01.y, w1.y);
      ffma2(acc0[r], a23.x, w2.x); ffma2(acc1[r], a23.x, w2.y);
      ffma2(acc0[r], a23.y, w3.x); ffma2(acc1[r], a23.y, w3.y);
    }
  }

  #pragma unroll
  for (int r = 0; r < RPB; r++)
    scratch[(q * RPB + r) * 64 + ct] = make_ulonglong2(acc0[r], acc1[r]);
  __syncthreads();

  if (tid < 256) {                         // combine: 256 items
    const int ct2 = tid & 63;
    const int r2  = tid >> 6;
    float v0 = 0.0f, v1 = 0.0f, v2 = 0.0f, v3 = 0.0f;
    #pragma unroll
    for (int qq = 0; qq < 8; qq++) {
      ulonglong2 p = scratch[(qq * RPB + r2) * 64 + ct2];
      v0 += plo(p.x); v1 += phi(p.x);
      v2 += plo(p.y); v3 += phi(p.y);
    }
    if (RELU) {
      v0 = fmaxf(v0, 0.0f); v1 = fmaxf(v1, 0.0f);
      v2 = fmaxf(v2, 0.0f); v3 = fmaxf(v3, 0.0f);
    }
    if constexpr (DUPOUT) {
      float4* o4 = reinterpret_cast<float4*>(outD + (size_t)r2 * outStride + ct2 * 4);
      o4[0] = make_float4(v0, v0, v1, v1);
      o4[1] = make_float4(v2, v2, v3, v3);
    } else {
      *reinterpret_cast<float4*>(outS + (size_t)r2 * outStride + ct2 * 4) =
          make_float4(v0, v1, v2, v3);
    }
  }
  __syncthreads();
}

// ---------------- persistent kernel ------------------------------------------
__global__ void __launch_bounds__(TPB, 1) ode_kernel(
    const float* __restrict__ z0,  const float* __restrict__ ts,
    const float* __restrict__ W1,  const float* __restrict__ b1,
    const float* __restrict__ W2,  const float* __restrict__ b2,
    const float* __restrict__ W3,  const float* __restrict__ b3,
    const float* __restrict__ W4,  const float* __restrict__ b4,
    const float* __restrict__ P1,  const float* __restrict__ pb1,
    const float* __restrict__ P2,  const float* __restrict__ pb2,
    const float* __restrict__ P3,  const float* __restrict__ pb3,
    const float* __restrict__ P4,  const float* __restrict__ pb4,
    float* __restrict__ out)
{
  extern __shared__ char smem_raw[];
  Smem* S = reinterpret_cast<Smem*>(smem_raw);
  const int tid  = threadIdx.x;
  const int lane = tid & 31;
  const int wid  = tid >> 5;
  const int row0 = blockIdx.x * RPB;

  for (int e = tid; e < RPB * LAT; e += TPB) {
    int r = e >> 8, c = e & 255;
    float v = z0[(row0 + r) * LAT + c];
    S->z[r][c] = v;
    g_traj[((row0 + r) * TST + 0) * LAT + c] = v;
  }
  __syncthreads();

  float dt = (ts[1] - ts[0]) * 0.1f;
  int pbuf = 0;

  for (int seg = 0; seg < TST - 1; seg++) {
    const float t1v = ts[seg + 1];
    float t = ts[seg];

    for (int step = 0; step < 12; step++) {
      float remaining = t1v - t;
      if (!(remaining > 1e-10f)) break;
      float dt_try = fminf(dt, remaining);

      // ---- 7 RK stages ----
      for (int i = 0; i < 7; i++) {
        float ti = t + c_C[i] * dt_try;
        for (int e = tid; e < RPB * LAT; e += TPB) {
          int r = e >> 8, c = e & 255;
          float v = S->z[r][c];
          #pragma unroll
          for (int j = 0; j < 6; j++) {
            if (j < i) {
              float aij = c_A[i][j];
              if (aij != 0.0f) v += (dt_try * aij) * S->k[j][r][c];
            }
          }
          S->a[r][c] = make_float2(v, v);
        }
        if (tid < RPB) S->a[tid][256] = make_float2(ti, ti);
        __syncthreads();

        layer_n512<true>(W1, b1, &S->a [0][0], 264, &S->h1[0][0], 520, LAT + 1, tid, S->sc);
        layer_n512<true>(W2, b2, &S->h1[0][0], 520, &S->h2[0][0], 520, HID,     tid, S->sc);
        layer_n512<true>(W3, b3, &S->h2[0][0], 520, &S->h1[0][0], 520, HID,     tid, S->sc);
        layer_n256<false, false>(W4, b4, &S->h1[0][0], 520,
                                 nullptr, &S->k[i][0][0], LAT, HID, tid, S->sc);
      }

      // ---- z5, err, local partial (shfl reduction, 1 barrier) ----
      double part = 0.0;
      for (int e = tid; e < RPB * LAT; e += TPB) {
        int r = e >> 8, c = e & 255;
        float zo = S->z[r][c];
        float z5 = zo, err = 0.0f;
        #pragma unroll
        for (int i = 0; i < 7; i++) {
          float ki = S->k[i][r][c];
          float b5 = c_B5[i];
          if (b5 != 0.0f) z5 += (dt_try * b5) * ki;
          float d = c_D[i];
          if (d != 0.0f) err += (dt_try * d) * ki;
        }
        S->a[r][c] = make_float2(z5, z5);
        float sc = 1e-4f + 1e-3f * fmaxf(fabsf(zo), fabsf(z5));
        float ra = err / sc;
        part += (double)(ra * ra);
      }
      #pragma unroll
      for (int o = 16; o > 0; o >>= 1)
        part += __shfl_down_sync(0xffffffffu, part, o);
      if (lane == 0) S->red[wid] = part;
      __syncthreads();
      if (tid == 0) {
        double s = 0.0;
        #pragma unroll
        for (int w = 0; w < TPB / 32; w++) s += S->red[w];
        g_part[pbuf][blockIdx.x] = s;
      }

      grid_sync();                         // ONE grid barrier per step

      // scalar step logic: warp 0 computes (deterministic, same in all CTAs)
      if (wid == 0) {
        double s = 0.0;
        #pragma unroll
        for (int j = 0; j < NCTA / 32; j++) s += g_part[pbuf][lane + j * 32];
        #pragma unroll
        for (int o = 16; o > 0; o >>= 1)
          s += __shfl_down_sync(0xffffffffu, s, o);
        if (lane == 0) {
          float en = sqrtf((float)(s / (double)(BSZ * LAT)));
          S->bcast[0] = (en <= 1.0f) ? 1.0f : 0.0f;
          S->bcast[1] = fminf(fmaxf(0.9f * powf(fmaxf(en, 1e-9f), -0.2f), 0.2f), 10.0f);
        }
      }
      __syncthreads();
      bool accept  = (S->bcast[0] != 0.0f);
      float factor = S->bcast[1];

      if (accept) {
        for (int e = tid; e < RPB * LAT; e += TPB) {
          int r = e >> 8, c = e & 255;
          S->z[r][c] = S->a[r][c].x;
        }
        t = t + dt_try;
      }
      dt = dt_try * factor;
      pbuf ^= 1;
      __syncthreads();
    }

    for (int e = tid; e < RPB * LAT; e += TPB) {
      int r = e >> 8, c = e & 255;
      g_traj[((row0 + r) * TST + (seg + 1)) * LAT + c] = S->z[r][c];
    }
    __syncthreads();
  }

  // ---- pose head (runs once; small share of total) ----
  for (int tix = 0; tix < TST; tix++) {
    for (int e = tid; e < RPB * LAT; e += TPB) {
      int r = e >> 8, c = e & 255;
      float v = g_traj[((row0 + r) * TST + tix) * LAT + c];
      S->a[r][c] = make_float2(v, v);
    }
    __syncthreads();

    layer_n512<true>(P1, pb1, &S->a[0][0], 264, &S->h1[0][0], 520, LAT, tid, S->sc);
    layer_n256<true, true>(P2, pb2, &S->h1[0][0], 520,
                           &S->h2[0][0], nullptr, 520, 512, tid, S->sc);

    // P3: 256 -> 128 (tiny), 128 threads, all rows
    if (tid < 128) {
      float acc[RPB];
      #pragma unroll
      for (int r = 0; r < RPB; r++) acc[r] = pb3[tid];
      #pragma unroll 4
      for (int k = 0; k < 256; k++) {
        float wv = P3[k * 128 + tid];
        #pragma unroll
        for (int r = 0; r < RPB; r++)
          acc[r] = fmaf(S->h2[r][k].x, wv, acc[r]);
      }
      #pragma unroll
      for (int r = 0; r < RPB; r++) {
        float v = fmaxf(acc[r], 0.0f);
        S->h1[r][tid] = make_float2(v, v);
      }
    }
    __syncthreads();

    if (tid < RPB * 7) {                   // final 128 -> 7
      int r = tid / 7, c = tid % 7;
      float acc = pb4[c];
      #pragma unroll 4
      for (int kk = 0; kk < 128; kk++)
        acc = fmaf(S->h1[r][kk].x, P4[kk * 7 + c], acc);
      S->z[r][c] = acc;
    }
    __syncthreads();

    if (tid < RPB) {
      int r = tid;
      float q0 = S->z[r][3], q1 = S->z[r][4], q2 = S->z[r][5], q3 = S->z[r][6];
      float nrm = sqrtf(q0*q0 + q1*q1 + q2*q2 + q3*q3);
      float dn  = fmaxf(nrm, 1e-12f);
      float* o = out + ((size_t)(row0 + r) * TST + tix) * 7;
      o[0] = S->z[r][0]; o[1] = S->z[r][1]; o[2] = S->z[r][2];
      o[3] = q0 / dn; o[4] = q1 / dn; o[5] = q2 / dn; o[6] = q3 / dn;
    }
    __syncthreads();
  }
}

// ---------------- launch ------------------------------------------------------
extern "C" void kernel_launch(void* const* d_in, const int* in_sizes, int n_in,
                              void* d_out, int out_size) {
  (void)in_sizes; (void)n_in; (void)out_size;
  const float* z0  = (const float*)d_in[0];
  const float* ts  = (const float*)d_in[1];
  const float* W1  = (const float*)d_in[2];
  const float* b1  = (const float*)d_in[3];
  const float* W2  = (const float*)d_in[4];
  const float* b2  = (const float*)d_in[5];
  const float* W3  = (const float*)d_in[6];
  const float* b3  = (const float*)d_in[7];
  const float* W4  = (const float*)d_in[8];
  const float* b4  = (const float*)d_in[9];
  const float* P1  = (const float*)d_in[10];
  const float* pb1 = (const float*)d_in[11];
  const float* P2  = (const float*)d_in[12];
  const float* pb2 = (const float*)d_in[13];
  const float* P3  = (const float*)d_in[14];
  const float* pb3 = (const float*)d_in[15];
  const float* P4  = (const float*)d_in[16];
  const float* pb4 = (const float*)d_in[17];
  float* out = (float*)d_out;

  cudaFuncSetAttribute(ode_kernel, cudaFuncAttributeMaxDynamicSharedMemorySize,
                       SMEM_BYTES);
  ode_kernel<<<NCTA, TPB, SMEM_BYTES>>>(z0, ts, W1, b1, W2, b2, W3, b3, W4, b4,
                                        P1, pb1, P2, pb2, P3, pb3, P4, pb4, out);
}

// round 15
// speedup vs baseline: 1.4103x; 1.3399x over previous
#include <cuda_runtime.h>
#include <math.h>

#define NCTA 128
#define TPB  512
#define RPB  4          // batch rows per CTA: 128*4 = 512
#define BSZ  512
#define LAT  256
#define HID  512
#define TST  8

typedef unsigned long long ull;

// ---------------- device scratch --------------------------------------------
__device__ float  g_traj[BSZ * TST * LAT];
__device__ double g_part[2][NCTA];
__device__ unsigned g_bar_gen = 0;
__device__ unsigned g_bar_cnt = 0;

// ---------------- Dormand-Prince tableau ------------------------------------
__constant__ float c_C[7] = {0.0f, 0.2f, 0.3f, 0.8f, (float)(8.0/9.0), 1.0f, 1.0f};
__constant__ float c_A[7][6] = {
  {0,0,0,0,0,0},
  {0.2f,0,0,0,0,0},
  {(float)(3.0/40.0),(float)(9.0/40.0),0,0,0,0},
  {(float)(44.0/45.0),(float)(-56.0/15.0),(float)(32.0/9.0),0,0,0},
  {(float)(19372.0/6561.0),(float)(-25360.0/2187.0),(float)(64448.0/6561.0),(float)(-212.0/729.0),0,0},
  {(float)(9017.0/3168.0),(float)(-355.0/33.0),(float)(46732.0/5247.0),(float)(49.0/176.0),(float)(-5103.0/18656.0),0},
  {(float)(35.0/384.0),0.0f,(float)(500.0/1113.0),(float)(125.0/192.0),(float)(-2187.0/6784.0),(float)(11.0/84.0)}
};
__constant__ float c_B5[7] = {
  (float)(35.0/384.0), 0.0f, (float)(500.0/1113.0), (float)(125.0/192.0),
  (float)(-2187.0/6784.0), (float)(11.0/84.0), 0.0f};
__constant__ float c_D[7] = {
  (float)(35.0/384.0 - 5179.0/57600.0), 0.0f,
  (float)(500.0/1113.0 - 7571.0/16695.0),
  (float)(125.0/192.0 - 393.0/640.0),
  (float)(-2187.0/6784.0 + 92097.0/339200.0),
  (float)(11.0/84.0 - 187.0/2100.0),
  (float)(-1.0/40.0)};

// ---------------- shared memory layout --------------------------------------
// Activations stored DUPLICATED: element (r,c) is float2{v,v}; LDS.128 yields
// two ready-made f32x2 splat operands for fma.rn.f32x2 (broadcast, no conflicts).
struct __align__(16) Smem {
  float  z [RPB][LAT];            // 4 KB
  float  k [7][RPB][LAT];         // 28 KB
  float2 a [RPB][264];            // 8.25 KB
  float2 h1[RPB][520];            // 16.25 KB
  float2 h2[RPB][520];            // 16.25 KB
  ulonglong2 sc[2048];            // 32 KB split-K partial pairs (both layouts)
  double red[16];                 // warp partials
  float  bcast[2];                // accept flag, factor
};
#define SMEM_BYTES ((int)sizeof(Smem))

// ---------------- packed fp32 FMA (sm_103a FFMA2) ---------------------------
__device__ __forceinline__ void ffma2(ull& d, ull a, ull b) {
  asm("fma.rn.f32x2 %0, %1, %2, %0;" : "+l"(d) : "l"(a), "l"(b));
}
__device__ __forceinline__ float plo(ull v) { return __uint_as_float((unsigned)v); }
__device__ __forceinline__ float phi(ull v) { return __uint_as_float((unsigned)(v >> 32)); }

// ---------------- manual grid barrier ----------------------------------------
__device__ __forceinline__ void grid_sync() {
  __syncthreads();
  if (threadIdx.x == 0) {
    __threadfence();
    unsigned gen = *(volatile unsigned*)&g_bar_gen;
    unsigned arrived = atomicAdd(&g_bar_cnt, 1u);
    if (arrived == NCTA - 1u) {
      atomicExch(&g_bar_cnt, 0u);
      __threadfence();
      atomicAdd(&g_bar_gen, 1u);
    } else {
      while (*(volatile unsigned*)&g_bar_gen == gen) { __nanosleep(64); }
    }
    __threadfence();
  }
  __syncthreads();
}

// ---------------- N=512 layer, CP=2, split-K x4 (R12, validated) -------------
// 128 col-threads (tid&127) each own 4 columns; group q = tid>>7 takes quarter
// q of K (group 3 absorbs the K=257 tail). All groups spill partials; ALL 512
// threads combine (one (col-thread,row) item each).
template<bool RELU>
__device__ __forceinline__ void layer_n512(
    const float* __restrict__ W, const float* __restrict__ bias,
    const float2* __restrict__ inD, int inStride,
    float2* __restrict__ outD, int outStride,
    int K, int tid, ulonglong2* __restrict__ scratch)
{
  const int ct = tid & 127;
  const int q  = tid >> 7;
  const int n0 = ct * 4;
  const int Kq = K >> 2;
  const int kstart = q * Kq;
  const int kend   = (q == 3) ? K : kstart + Kq;

  ull acc0[RPB], acc1[RPB];
  ull b0 = 0, b1 = 0;
  if (q == 0) {
    ulonglong2 bv = *reinterpret_cast<const ulonglong2*>(bias + n0);
    b0 = bv.x; b1 = bv.y;
  }
  #pragma unroll
  for (int r = 0; r < RPB; r++) { acc0[r] = b0; acc1[r] = b1; }

  int k = kstart;
  #pragma unroll 2
  for (; k + 4 <= kend; k += 4) {
    const float* Wk = W + (size_t)k * 512 + n0;
    ulonglong2 w0 = *reinterpret_cast<const ulonglong2*>(Wk);
    ulonglong2 w1 = *reinterpret_cast<const ulonglong2*>(Wk + 512);
    ulonglong2 w2 = *reinterpret_cast<const ulonglong2*>(Wk + 1024);
    ulonglong2 w3 = *reinterpret_cast<const ulonglong2*>(Wk + 1536);
    #pragma unroll
    for (int r = 0; r < RPB; r++) {
      const ulonglong2* ap =
          reinterpret_cast<const ulonglong2*>(inD + (size_t)r * inStride + k);
      ulonglong2 a01 = ap[0];
      ulonglong2 a23 = ap[1];
      ffma2(acc0[r], a01.x, w0.x); ffma2(acc1[r], a01.x, w0.y);
      ffma2(acc0[r], a01.y, w1.x); ffma2(acc1[r], a01.y, w1.y);
      ffma2(acc0[r], a23.x, w2.x); ffma2(acc1[r], a23.x, w2.y);
      ffma2(acc0[r], a23.y, w3.x); ffma2(acc1[r], a23.y, w3.y);
    }
  }
  for (; k < kend; k++) {                  // tail (K=257: k=256, group 3 only)
    ulonglong2 w = *reinterpret_cast<const ulonglong2*>(W + (size_t)k * 512 + n0);
    #pragma unroll
    for (int r = 0; r < RPB; r++) {
      ull av = *reinterpret_cast<const ull*>(inD + (size_t)r * inStride + k);
      ffma2(acc0[r], av, w.x); ffma2(acc1[r], av, w.y);
    }
  }

  #pragma unroll
  for (int r = 0; r < RPB; r++)
    scratch[(q * RPB + r) * 128 + ct] = make_ulonglong2(acc0[r], acc1[r]);
  __syncthreads();

  // parallel combine: 512 threads, one (col-thread, row) item each
  {
    const int ct2 = tid & 127;
    const int r2  = tid >> 7;
    float v0 = 0.0f, v1 = 0.0f, v2 = 0.0f, v3 = 0.0f;
    #pragma unroll
    for (int qq = 0; qq < 4; qq++) {
      ulonglong2 p = scratch[(qq * RPB + r2) * 128 + ct2];
      v0 += plo(p.x); v1 += phi(p.x);
      v2 += plo(p.y); v3 += phi(p.y);
    }
    if (RELU) {
      v0 = fmaxf(v0, 0.0f); v1 = fmaxf(v1, 0.0f);
      v2 = fmaxf(v2, 0.0f); v3 = fmaxf(v3, 0.0f);
    }
    float4* o4 = reinterpret_cast<float4*>(outD + (size_t)r2 * outStride + ct2 * 4);
    o4[0] = make_float4(v0, v0, v1, v1);
    o4[1] = make_float4(v2, v2, v3, v3);
  }
  __syncthreads();
}

// ---------------- N=256 layer, CP=2, split-K x8 (R12, validated) -------------
// 64 col-threads (tid&63) own 4 columns each; group q = tid>>6 takes eighth q
// of K (K=512 at both call sites). Parallel combine on 256 threads.
template<bool RELU, bool DUPOUT>
__device__ __forceinline__ void layer_n256(
    const float* __restrict__ W, const float* __restrict__ bias,
    const float2* __restrict__ inD, int inStride,
    float2* __restrict__ outD, float* __restrict__ outS, int outStride,
    int K, int tid, ulonglong2* __restrict__ scratch)
{
  const int ct = tid & 63;
  const int q  = tid >> 6;
  const int n0 = ct * 4;
  const int Kq = K >> 3;
  const int kstart = q * Kq;
  const int kend   = kstart + Kq;

  ull acc0[RPB], acc1[RPB];
  ull b0 = 0, b1 = 0;
  if (q == 0) {
    ulonglong2 bv = *reinterpret_cast<const ulonglong2*>(bias + n0);
    b0 = bv.x; b1 = bv.y;
  }
  #pragma unroll
  for (int r = 0; r < RPB; r++) { acc0[r] = b0; acc1[r] = b1; }

  int k = kstart;
  #pragma unroll 2
  for (; k + 4 <= kend; k += 4) {
    const float* Wk = W + (size_t)k * 256 + n0;
    ulonglong2 w0 = *reinterpret_cast<const ulonglong2*>(Wk);
    ulonglong2 w1 = *reinterpret_cast<const ulonglong2*>(Wk + 256);
    ulonglong2 w2 = *reinterpret_cast<const ulonglong2*>(Wk + 512);
    ulonglong2 w3 = *reinterpret_cast<const ulonglong2*>(Wk + 768);
    #pragma unroll
    for (int r = 0; r < RPB; r++) {
      const ulonglong2* ap =
          reinterpret_cast<const ulonglong2*>(inD + (size_t)r * inStride + k);
      ulonglong2 a01 = ap[0];
      ulonglong2 a23 = ap[1];
      ffma2(acc0[r], a01.x, w0.x); ffma2(acc1[r], a01.x, w0.y);
      ffma2(acc0[r], a01.y, w1.x); ffma2(acc1[r], a01.y, w1.y);
      ffma2(acc0[r], a23.x, w2.x); ffma2(acc1[r], a23.x, w2.y);
      ffma2(acc0[r], a23.y, w3.x); ffma2(acc1[r], a23.y, w3.y);
    }
  }

  #pragma unroll
  for (int r = 0; r < RPB; r++)
    scratch[(q * RPB + r) * 64 + ct] = make_ulonglong2(acc0[r], acc1[r]);
  __syncthreads();

  if (tid < 256) {                         // combine: 256 items
    const int ct2 = tid & 63;
    const int r2  = tid >> 6;
    float v0 = 0.0f, v1 = 0.0f, v2 = 0.0f, v3 = 0.0f;
    #pragma unroll
    for (int qq = 0; qq < 8; qq++) {
      ulonglong2 p = scratch[(qq * RPB + r2) * 64 + ct2];
      v0 += plo(p.x); v1 += phi(p.x);
      v2 += plo(p.y); v3 += phi(p.y);
    }
    if (RELU) {
      v0 = fmaxf(v0, 0.0f); v1 = fmaxf(v1, 0.0f);
      v2 = fmaxf(v2, 0.0f); v3 = fmaxf(v3, 0.0f);
    }
    if constexpr (DUPOUT) {
      float4* o4 = reinterpret_cast<float4*>(outD + (size_t)r2 * outStride + ct2 * 4);
      o4[0] = make_float4(v0, v0, v1, v1);
      o4[1] = make_float4(v2, v2, v3, v3);
    } else {
      *reinterpret_cast<float4*>(outS + (size_t)r2 * outStride + ct2 * 4) =
          make_float4(v0, v1, v2, v3);
    }
  }
  __syncthreads();
}

// ---------------- persistent kernel ------------------------------------------
__global__ void __launch_bounds__(TPB, 1) ode_kernel(
    const float* __restrict__ z0,  const float* __restrict__ ts,
    const float* __restrict__ W1,  const float* __restrict__ b1,
    const float* __restrict__ W2,  const float* __restrict__ b2,
    const float* __restrict__ W3,  const float* __restrict__ b3,
    const float* __restrict__ W4,  const float* __restrict__ b4,
    const float* __restrict__ P1,  const float* __restrict__ pb1,
    const float* __restrict__ P2,  const float* __restrict__ pb2,
    const float* __restrict__ P3,  const float* __restrict__ pb3,
    const float* __restrict__ P4,  const float* __restrict__ pb4,
    float* __restrict__ out)
{
  extern __shared__ char smem_raw[];
  Smem* S = reinterpret_cast<Smem*>(smem_raw);
  const int tid  = threadIdx.x;
  const int lane = tid & 31;
  const int wid  = tid >> 5;
  const int row0 = blockIdx.x * RPB;

  for (int e = tid; e < RPB * LAT; e += TPB) {
    int r = e >> 8, c = e & 255;
    float v = z0[(row0 + r) * LAT + c];
    S->z[r][c] = v;
    g_traj[((row0 + r) * TST + 0) * LAT + c] = v;
  }
  __syncthreads();

  float dt = (ts[1] - ts[0]) * 0.1f;
  int pbuf = 0;

  // FSAL state: k[0] holds f(k1_t, z) when k1_valid (uniform across threads).
  bool  k1_valid = false;
  float k1_t     = 0.0f;

  for (int seg = 0; seg < TST - 1; seg++) {
    const float t1v = ts[seg + 1];
    float t = ts[seg];

    for (int step = 0; step < 12; step++) {
      float remaining = t1v - t;
      if (!(remaining > 1e-10f)) break;
      float dt_try = fminf(dt, remaining);

      // ---- 7 RK stages (stage 0 skipped via FSAL when k1 is current) ----
      for (int i = 0; i < 7; i++) {
        if (i == 0 && k1_valid && k1_t == t) continue;   // k1 == stored k[0]
        float ti = t + c_C[i] * dt_try;
        for (int e = tid; e < RPB * LAT; e += TPB) {
          int r = e >> 8, c = e & 255;
          float v = S->z[r][c];
          #pragma unroll
          for (int j = 0; j < 6; j++) {
            if (j < i) {
              float aij = c_A[i][j];
              if (aij != 0.0f) v += (dt_try * aij) * S->k[j][r][c];
            }
          }
          S->a[r][c] = make_float2(v, v);
        }
        if (tid < RPB) S->a[tid][256] = make_float2(ti, ti);
        __syncthreads();

        layer_n512<true>(W1, b1, &S->a [0][0], 264, &S->h1[0][0], 520, LAT + 1, tid, S->sc);
        layer_n512<true>(W2, b2, &S->h1[0][0], 520, &S->h2[0][0], 520, HID,     tid, S->sc);
        layer_n512<true>(W3, b3, &S->h2[0][0], 520, &S->h1[0][0], 520, HID,     tid, S->sc);
        layer_n256<false, false>(W4, b4, &S->h1[0][0], 520,
                                 nullptr, &S->k[i][0][0], LAT, HID, tid, S->sc);
      }

      // ---- z5, err, local partial (shfl reduction) ----
      double part = 0.0;
      for (int e = tid; e < RPB * LAT; e += TPB) {
        int r = e >> 8, c = e & 255;
        float zo = S->z[r][c];
        float z5 = zo, err = 0.0f;
        #pragma unroll
        for (int i = 0; i < 7; i++) {
          float ki = S->k[i][r][c];
          float b5 = c_B5[i];
          if (b5 != 0.0f) z5 += (dt_try * b5) * ki;
          float d = c_D[i];
          if (d != 0.0f) err += (dt_try * d) * ki;
        }
        S->a[r][c] = make_float2(z5, z5);
        float sc = 1e-4f + 1e-3f * fmaxf(fabsf(zo), fabsf(z5));
        float ra = err / sc;
        part += (double)(ra * ra);
      }
      #pragma unroll
      for (int o = 16; o > 0; o >>= 1)
        part += __shfl_down_sync(0xffffffffu, part, o);
      if (lane == 0) S->red[wid] = part;
      __syncthreads();
      if (tid == 0) {
        double s = 0.0;
        #pragma unroll
        for (int w = 0; w < TPB / 32; w++) s += S->red[w];
        g_part[pbuf][blockIdx.x] = s;
      }

      grid_sync();                         // ONE grid barrier per step

      // scalar step logic: warp 0 computes (deterministic, same in all CTAs)
      if (wid == 0) {
        double s = 0.0;
        #pragma unroll
        for (int j = 0; j < NCTA / 32; j++) s += g_part[pbuf][lane + j * 32];
        #pragma unroll
        for (int o = 16; o > 0; o >>= 1)
          s += __shfl_down_sync(0xffffffffu, s, o);
        if (lane == 0) {
          float en = sqrtf((float)(s / (double)(BSZ * LAT)));
          S->bcast[0] = (en <= 1.0f) ? 1.0f : 0.0f;
          S->bcast[1] = fminf(fmaxf(0.9f * powf(fmaxf(en, 1e-9f), -0.2f), 0.2f), 10.0f);
        }
      }
      __syncthreads();
      bool accept  = (S->bcast[0] != 0.0f);
      float factor = S->bcast[1];

      if (accept) {
        // z <- z5; FSAL: k1(next) = k7 = f(t+dt, z5), bitwise (A[6] == B5)
        for (int e = tid; e < RPB * LAT; e += TPB) {
          int r = e >> 8, c = e & 255;
          S->z[r][c]    = S->a[r][c].x;
          S->k[0][r][c] = S->k[6][r][c];
        }
        t = t + dt_try;
      }
      // on reject: (t,z) unchanged -> old k[0] still f(t,z)
      k1_valid = true;
      k1_t     = t;
      dt = dt_try * factor;
      pbuf ^= 1;
      __syncthreads();
    }

    for (int e = tid; e < RPB * LAT; e += TPB) {
      int r = e >> 8, c = e & 255;
      g_traj[((row0 + r) * TST + (seg + 1)) * LAT + c] = S->z[r][c];
    }
    __syncthreads();
  }

  // ---- pose head (runs once; small share of total) ----
  for (int tix = 0; tix < TST; tix++) {
    for (int e = tid; e < RPB * LAT; e += TPB) {
      int r = e >> 8, c = e & 255;
      float v = g_traj[((row0 + r) * TST + tix) * LAT + c];
      S->a[r][c] = make_float2(v, v);
    }
    __syncthreads();

    layer_n512<true>(P1, pb1, &S->a[0][0], 264, &S->h1[0][0], 520, LAT, tid, S->sc);
    layer_n256<true, true>(P2, pb2, &S->h1[0][0], 520,
                           &S->h2[0][0], nullptr, 520, 512, tid, S->sc);

    // P3: 256 -> 128 (tiny), 128 threads, all rows
    if (tid < 128) {
      float acc[RPB];
      #pragma unroll
      for (int r = 0; r < RPB; r++) acc[r] = pb3[tid];
      #pragma unroll 4
      for (int k = 0; k < 256; k++) {
        float wv = P3[k * 128 + tid];
        #pragma unroll
        for (int r = 0; r < RPB; r++)
          acc[r] = fmaf(S->h2[r][k].x, wv, acc[r]);
      }
      #pragma unroll
      for (int r = 0; r < RPB; r++) {
        float v = fmaxf(acc[r], 0.0f);
        S->h1[r][tid] = make_float2(v, v);
      }
    }
    __syncthreads();

    if (tid < RPB * 7) {                   // final 128 -> 7
      int r = tid / 7, c = tid % 7;
      float acc = pb4[c];
      #pragma unroll 4
      for (int kk = 0; kk < 128; kk++)
        acc = fmaf(S->h1[r][kk].x, P4[kk * 7 + c], acc);
      S->z[r][c] = acc;
    }
    __syncthreads();

    if (tid < RPB) {
      int r = tid;
      float q0 = S->z[r][3], q1 = S->z[r][4], q2 = S->z[r][5], q3 = S->z[r][6];
      float nrm = sqrtf(q0*q0 + q1*q1 + q2*q2 + q3*q3);
      float dn  = fmaxf(nrm, 1e-12f);
      float* o = out + ((size_t)(row0 + r) * TST + tix) * 7;
      o[0] = S->z[r][0]; o[1] = S->z[r][1]; o[2] = S->z[r][2];
      o[3] = q0 / dn; o[4] = q1 / dn; o[5] = q2 / dn; o[6] = q3 / dn;
    }
    __syncthreads();
  }
}

// ---------------- launch ------------------------------------------------------
extern "C" void kernel_launch(void* const* d_in, const int* in_sizes, int n_in,
                              void* d_out, int out_size) {
  (void)in_sizes; (void)n_in; (void)out_size;
  const float* z0  = (const float*)d_in[0];
  const float* ts  = (const float*)d_in[1];
  const float* W1  = (const float*)d_in[2];
  const float* b1  = (const float*)d_in[3];
  const float* W2  = (const float*)d_in[4];
  const float* b2  = (const float*)d_in[5];
  const float* W3  = (const float*)d_in[6];
  const float* b3  = (const float*)d_in[7];
  const float* W4  = (const float*)d_in[8];
  const float* b4  = (const float*)d_in[9];
  const float* P1  = (const float*)d_in[10];
  const float* pb1 = (const float*)d_in[11];
  const float* P2  = (const float*)d_in[12];
  const float* pb2 = (const float*)d_in[13];
  const float* P3  = (const float*)d_in[14];
  const float* pb3 = (const float*)d_in[15];
  const float* P4  = (const float*)d_in[16];
  const float* pb4 = (const float*)d_in[17];
  float* out = (float*)d_out;

  cudaFuncSetAttribute(ode_kernel, cudaFuncAttributeMaxDynamicSharedMemorySize,
                       SMEM_BYTES);
  ode_kernel<<<NCTA, TPB, SMEM_BYTES>>>(z0, ts, W1, b1, W2, b2, W3, b3, W4, b4,
                                        P1, pb1, P2, pb2, P3, pb3, P4, pb4, out);
}

// round 16
// speedup vs baseline: 1.4122x; 1.0013x over previous
#include <cuda_runtime.h>
#include <math.h>

#define NCTA 128
#define TPB  512
#define RPB  4          // batch rows per CTA: 128*4 = 512
#define BSZ  512
#define LAT  256
#define HID  512
#define TST  8

typedef unsigned long long ull;

// ---------------- device scratch --------------------------------------------
__device__ float  g_traj[BSZ * TST * LAT];
__device__ double g_part[2][NCTA];
__device__ unsigned g_bar_gen = 0;
__device__ unsigned g_bar_cnt = 0;

// ---------------- Dormand-Prince tableau ------------------------------------
__constant__ float c_C[7] = {0.0f, 0.2f, 0.3f, 0.8f, (float)(8.0/9.0), 1.0f, 1.0f};
__constant__ float c_A[7][6] = {
  {0,0,0,0,0,0},
  {0.2f,0,0,0,0,0},
  {(float)(3.0/40.0),(float)(9.0/40.0),0,0,0,0},
  {(float)(44.0/45.0),(float)(-56.0/15.0),(float)(32.0/9.0),0,0,0},
  {(float)(19372.0/6561.0),(float)(-25360.0/2187.0),(float)(64448.0/6561.0),(float)(-212.0/729.0),0,0},
  {(float)(9017.0/3168.0),(float)(-355.0/33.0),(float)(46732.0/5247.0),(float)(49.0/176.0),(float)(-5103.0/18656.0),0},
  {(float)(35.0/384.0),0.0f,(float)(500.0/1113.0),(float)(125.0/192.0),(float)(-2187.0/6784.0),(float)(11.0/84.0)}
};
__constant__ float c_B5[7] = {
  (float)(35.0/384.0), 0.0f, (float)(500.0/1113.0), (float)(125.0/192.0),
  (float)(-2187.0/6784.0), (float)(11.0/84.0), 0.0f};
__constant__ float c_D[7] = {
  (float)(35.0/384.0 - 5179.0/57600.0), 0.0f,
  (float)(500.0/1113.0 - 7571.0/16695.0),
  (float)(125.0/192.0 - 393.0/640.0),
  (float)(-2187.0/6784.0 + 92097.0/339200.0),
  (float)(11.0/84.0 - 187.0/2100.0),
  (float)(-1.0/40.0)};

// ---------------- shared memory layout --------------------------------------
// Activations stored DUPLICATED: element (r,c) is float2{v,v}; LDS.128 yields
// two ready-made f32x2 splat operands for fma.rn.f32x2 (broadcast, no conflicts).
struct __align__(16) Smem {
  float  z [RPB][LAT];            // 4 KB
  float  k [7][RPB][LAT];         // 28 KB
  float2 a [RPB][264];            // 8.25 KB
  float2 h1[RPB][520];            // 16.25 KB
  float2 h2[RPB][520];            // 16.25 KB
  ulonglong2 sc[2048];            // 32 KB split-K partial pairs (both layouts)
  double red[16];                 // warp partials
  float  bcast[2];                // accept flag, factor
};
#define SMEM_BYTES ((int)sizeof(Smem))

// ---------------- packed fp32 FMA (sm_103a FFMA2) ---------------------------
__device__ __forceinline__ void ffma2(ull& d, ull a, ull b) {
  asm("fma.rn.f32x2 %0, %1, %2, %0;" : "+l"(d) : "l"(a), "l"(b));
}
__device__ __forceinline__ float plo(ull v) { return __uint_as_float((unsigned)v); }
__device__ __forceinline__ float phi(ull v) { return __uint_as_float((unsigned)(v >> 32)); }

// ---------------- manual grid barrier ----------------------------------------
__device__ __forceinline__ void grid_sync() {
  __syncthreads();
  if (threadIdx.x == 0) {
    __threadfence();
    unsigned gen = *(volatile unsigned*)&g_bar_gen;
    unsigned arrived = atomicAdd(&g_bar_cnt, 1u);
    if (arrived == NCTA - 1u) {
      atomicExch(&g_bar_cnt, 0u);
      __threadfence();
      atomicAdd(&g_bar_gen, 1u);
    } else {
      while (*(volatile unsigned*)&g_bar_gen == gen) { __nanosleep(64); }
    }
    __threadfence();
  }
  __syncthreads();
}

// ---------------- N=512 layer, CP=2, split-K x4 (R12, validated) -------------
// 128 col-threads (tid&127) each own 4 columns; group q = tid>>7 takes quarter
// q of K (group 3 absorbs the K=257 tail). All groups spill partials; ALL 512
// threads combine (one (col-thread,row) item each).
template<bool RELU>
__device__ __forceinline__ void layer_n512(
    const float* __restrict__ W, const float* __restrict__ bias,
    const float2* __restrict__ inD, int inStride,
    float2* __restrict__ outD, int outStride,
    int K, int tid, ulonglong2* __restrict__ scratch)
{
  const int ct = tid & 127;
  const int q  = tid >> 7;
  const int n0 = ct * 4;
  const int Kq = K >> 2;
  const int kstart = q * Kq;
  const int kend   = (q == 3) ? K : kstart + Kq;

  ull acc0[RPB], acc1[RPB];
  ull b0 = 0, b1 = 0;
  if (q == 0) {
    ulonglong2 bv = *reinterpret_cast<const ulonglong2*>(bias + n0);
    b0 = bv.x; b1 = bv.y;
  }
  #pragma unroll
  for (int r = 0; r < RPB; r++) { acc0[r] = b0; acc1[r] = b1; }

  int k = kstart;
  #pragma unroll 2
  for (; k + 4 <= kend; k += 4) {
    const float* Wk = W + (size_t)k * 512 + n0;
    ulonglong2 w0 = *reinterpret_cast<const ulonglong2*>(Wk);
    ulonglong2 w1 = *reinterpret_cast<const ulonglong2*>(Wk + 512);
    ulonglong2 w2 = *reinterpret_cast<const ulonglong2*>(Wk + 1024);
    ulonglong2 w3 = *reinterpret_cast<const ulonglong2*>(Wk + 1536);
    #pragma unroll
    for (int r = 0; r < RPB; r++) {
      const ulonglong2* ap =
          reinterpret_cast<const ulonglong2*>(inD + (size_t)r * inStride + k);
      ulonglong2 a01 = ap[0];
      ulonglong2 a23 = ap[1];
      ffma2(acc0[r], a01.x, w0.x); ffma2(acc1[r], a01.x, w0.y);
      ffma2(acc0[r], a01.y, w1.x); ffma2(acc1[r], a01.y, w1.y);
      ffma2(acc0[r], a23.x, w2.x); ffma2(acc1[r], a23.x, w2.y);
      ffma2(acc0[r], a23.y, w3.x); ffma2(acc1[r], a23.y, w3.y);
    }
  }
  for (; k < kend; k++) {                  // tail (K=257: k=256, group 3 only)
    ulonglong2 w = *reinterpret_cast<const ulonglong2*>(W + (size_t)k * 512 + n0);
    #pragma unroll
    for (int r = 0; r < RPB; r++) {
      ull av = *reinterpret_cast<const ull*>(inD + (size_t)r * inStride + k);
      ffma2(acc0[r], av, w.x); ffma2(acc1[r], av, w.y);
    }
  }

  #pragma unroll
  for (int r = 0; r < RPB; r++)
    scratch[(q * RPB + r) * 128 + ct] = make_ulonglong2(acc0[r], acc1[r]);
  __syncthreads();

  // parallel combine: 512 threads, one (col-thread, row) item each
  {
    const int ct2 = tid & 127;
    const int r2  = tid >> 7;
    float v0 = 0.0f, v1 = 0.0f, v2 = 0.0f, v3 = 0.0f;
    #pragma unroll
    for (int qq = 0; qq < 4; qq++) {
      ulonglong2 p = scratch[(qq * RPB + r2) * 128 + ct2];
      v0 += plo(p.x); v1 += phi(p.x);
      v2 += plo(p.y); v3 += phi(p.y);
    }
    if (RELU) {
      v0 = fmaxf(v0, 0.0f); v1 = fmaxf(v1, 0.0f);
      v2 = fmaxf(v2, 0.0f); v3 = fmaxf(v3, 0.0f);
    }
    float4* o4 = reinterpret_cast<float4*>(outD + (size_t)r2 * outStride + ct2 * 4);
    o4[0] = make_float4(v0, v0, v1, v1);
    o4[1] = make_float4(v2, v2, v3, v3);
  }
  __syncthreads();
}

// ---------------- N=256 layer, CP=2, split-K x8 (R12, validated) -------------
// 64 col-threads (tid&63) own 4 columns each; group q = tid>>6 takes eighth q
// of K (K=512 at both call sites). Parallel combine on 256 threads.
template<bool RELU, bool DUPOUT>
__device__ __forceinline__ void layer_n256(
    const float* __restrict__ W, const float* __restrict__ bias,
    const float2* __restrict__ inD, int inStride,
    float2* __restrict__ outD, float* __restrict__ outS, int outStride,
    int K, int tid, ulonglong2* __restrict__ scratch)
{
  const int ct = tid & 63;
  const int q  = tid >> 6;
  const int n0 = ct * 4;
  const int Kq = K >> 3;
  const int kstart = q * Kq;
  const int kend   = kstart + Kq;

  ull acc0[RPB], acc1[RPB];
  ull b0 = 0, b1 = 0;
  if (q == 0) {
    ulonglong2 bv = *reinterpret_cast<const ulonglong2*>(bias + n0);
    b0 = bv.x; b1 = bv.y;
  }
  #pragma unroll
  for (int r = 0; r < RPB; r++) { acc0[r] = b0; acc1[r] = b1; }

  int k = kstart;
  #pragma unroll 2
  for (; k + 4 <= kend; k += 4) {
    const float* Wk = W + (size_t)k * 256 + n0;
    ulonglong2 w0 = *reinterpret_cast<const ulonglong2*>(Wk);
    ulonglong2 w1 = *reinterpret_cast<const ulonglong2*>(Wk + 256);
    ulonglong2 w2 = *reinterpret_cast<const ulonglong2*>(Wk + 512);
    ulonglong2 w3 = *reinterpret_cast<const ulonglong2*>(Wk + 768);
    #pragma unroll
    for (int r = 0; r < RPB; r++) {
      const ulonglong2* ap =
          reinterpret_cast<const ulonglong2*>(inD + (size_t)r * inStride + k);
      ulonglong2 a01 = ap[0];
      ulonglong2 a23 = ap[1];
      ffma2(acc0[r], a01.x, w0.x); ffma2(acc1[r], a01.x, w0.y);
      ffma2(acc0[r], a01.y, w1.x); ffma2(acc1[r], a01.y, w1.y);
      ffma2(acc0[r], a23.x, w2.x); ffma2(acc1[r], a23.x, w2.y);
      ffma2(acc0[r], a23.y, w3.x); ffma2(acc1[r], a23.y, w3.y);
    }
  }

  #pragma unroll
  for (int r = 0; r < RPB; r++)
    scratch[(q * RPB + r) * 64 + ct] = make_ulonglong2(acc0[r], acc1[r]);
  __syncthreads();

  if (tid < 256) {                         // combine: 256 items
    const int ct2 = tid & 63;
    const int r2  = tid >> 6;
    float v0 = 0.0f, v1 = 0.0f, v2 = 0.0f, v3 = 0.0f;
    #pragma unroll
    for (int qq = 0; qq < 8; qq++) {
      ulonglong2 p = scratch[(qq * RPB + r2) * 64 + ct2];
      v0 += plo(p.x); v1 += phi(p.x);
      v2 += plo(p.y); v3 += phi(p.y);
    }
    if (RELU) {
      v0 = fmaxf(v0, 0.0f); v1 = fmaxf(v1, 0.0f);
      v2 = fmaxf(v2, 0.0f); v3 = fmaxf(v3, 0.0f);
    }
    if constexpr (DUPOUT) {
      float4* o4 = reinterpret_cast<float4*>(outD + (size_t)r2 * outStride + ct2 * 4);
      o4[0] = make_float4(v0, v0, v1, v1);
      o4[1] = make_float4(v2, v2, v3, v3);
    } else {
      *reinterpret_cast<float4*>(outS + (size_t)r2 * outStride + ct2 * 4) =
          make_float4(v0, v1, v2, v3);
    }
  }
  __syncthreads();
}

// ---------------- persistent kernel ------------------------------------------
__global__ void __launch_bounds__(TPB, 1) ode_kernel(
    const float* __restrict__ z0,  const float* __restrict__ ts,
    const float* __restrict__ W1,  const float* __restrict__ b1,
    const float* __restrict__ W2,  const float* __restrict__ b2,
    const float* __restrict__ W3,  const float* __restrict__ b3,
    const float* __restrict__ W4,  const float* __restrict__ b4,
    const float* __restrict__ P1,  const float* __restrict__ pb1,
    const float* __restrict__ P2,  const float* __restrict__ pb2,
    const float* __restrict__ P3,  const float* __restrict__ pb3,
    const float* __restrict__ P4,  const float* __restrict__ pb4,
    float* __restrict__ out)
{
  extern __shared__ char smem_raw[];
  Smem* S = reinterpret_cast<Smem*>(smem_raw);
  const int tid  = threadIdx.x;
  const int lane = tid & 31;
  const int wid  = tid >> 5;
  const int row0 = blockIdx.x * RPB;

  for (int e = tid; e < RPB * LAT; e += TPB) {
    int r = e >> 8, c = e & 255;
    float v = z0[(row0 + r) * LAT + c];
    S->z[r][c] = v;
    g_traj[((row0 + r) * TST + 0) * LAT + c] = v;
  }
  __syncthreads();

  float dt = (ts[1] - ts[0]) * 0.1f;
  int pbuf = 0;

  // FSAL state: k[0] holds f(k1_t, z) when k1_valid (uniform across threads).
  bool  k1_valid = false;
  float k1_t     = 0.0f;

  for (int seg = 0; seg < TST - 1; seg++) {
    const float t1v = ts[seg + 1];
    float t = ts[seg];

    for (int step = 0; step < 12; step++) {
      float remaining = t1v - t;
      if (!(remaining > 1e-10f)) break;
      float dt_try = fminf(dt, remaining);

      // ---- 7 RK stages (stage 0 skipped via FSAL when k1 is current) ----
      for (int i = 0; i < 7; i++) {
        if (i == 0 && k1_valid && k1_t == t) continue;   // k1 == stored k[0]
        float ti = t + c_C[i] * dt_try;
        for (int e = tid; e < RPB * LAT; e += TPB) {
          int r = e >> 8, c = e & 255;
          float v = S->z[r][c];
          #pragma unroll
          for (int j = 0; j < 6; j++) {
            if (j < i) {
              float aij = c_A[i][j];
              if (aij != 0.0f) v += (dt_try * aij) * S->k[j][r][c];
            }
          }
          S->a[r][c] = make_float2(v, v);
        }
        if (tid < RPB) S->a[tid][256] = make_float2(ti, ti);
        __syncthreads();

        layer_n512<true>(W1, b1, &S->a [0][0], 264, &S->h1[0][0], 520, LAT + 1, tid, S->sc);
        layer_n512<true>(W2, b2, &S->h1[0][0], 520, &S->h2[0][0], 520, HID,     tid, S->sc);
        layer_n512<true>(W3, b3, &S->h2[0][0], 520, &S->h1[0][0], 520, HID,     tid, S->sc);
        layer_n256<false, false>(W4, b4, &S->h1[0][0], 520,
                                 nullptr, &S->k[i][0][0], LAT, HID, tid, S->sc);
      }

      // ---- z5, err, local partial (shfl reduction) ----
      double part = 0.0;
      for (int e = tid; e < RPB * LAT; e += TPB) {
        int r = e >> 8, c = e & 255;
        float zo = S->z[r][c];
        float z5 = zo, err = 0.0f;
        #pragma unroll
        for (int i = 0; i < 7; i++) {
          float ki = S->k[i][r][c];
          float b5 = c_B5[i];
          if (b5 != 0.0f) z5 += (dt_try * b5) * ki;
          float d = c_D[i];
          if (d != 0.0f) err += (dt_try * d) * ki;
        }
        S->a[r][c] = make_float2(z5, z5);
        float sc = 1e-4f + 1e-3f * fmaxf(fabsf(zo), fabsf(z5));
        float ra = err / sc;
        part += (double)(ra * ra);
      }
      #pragma unroll
      for (int o = 16; o > 0; o >>= 1)
        part += __shfl_down_sync(0xffffffffu, part, o);
      if (lane == 0) S->red[wid] = part;
      __syncthreads();
      if (tid == 0) {
        double s = 0.0;
        #pragma unroll
        for (int w = 0; w < TPB / 32; w++) s += S->red[w];
        g_part[pbuf][blockIdx.x] = s;
      }

      grid_sync();                         // ONE grid barrier per step

      // scalar step logic: warp 0 computes (deterministic, same in all CTAs)
      if (wid == 0) {
        double s = 0.0;
        #pragma unroll
        for (int j = 0; j < NCTA / 32; j++) s += g_part[pbuf][lane + j * 32];
        #pragma unroll
        for (int o = 16; o > 0; o >>= 1)
          s += __shfl_down_sync(0xffffffffu, s, o);
        if (lane == 0) {
          float en = sqrtf((float)(s / (double)(BSZ * LAT)));
          S->bcast[0] = (en <= 1.0f) ? 1.0f : 0.0f;
          S->bcast[1] = fminf(fmaxf(0.9f * powf(fmaxf(en, 1e-9f), -0.2f), 0.2f), 10.0f);
        }
      }
      __syncthreads();
      bool accept  = (S->bcast[0] != 0.0f);
      float factor = S->bcast[1];

      if (accept) {
        // z <- z5; FSAL: k1(next) = k7 = f(t+dt, z5), bitwise (A[6] == B5)
        for (int e = tid; e < RPB * LAT; e += TPB) {
          int r = e >> 8, c = e & 255;
          S->z[r][c]    = S->a[r][c].x;
          S->k[0][r][c] = S->k[6][r][c];
        }
        t = t + dt_try;
      }
      // on reject: (t,z) unchanged -> old k[0] still f(t,z)
      k1_valid = true;
      k1_t     = t;
      dt = dt_try * factor;
      pbuf ^= 1;
      __syncthreads();
    }

    for (int e = tid; e < RPB * LAT; e += TPB) {
      int r = e >> 8, c = e & 255;
      g_traj[((row0 + r) * TST + (seg + 1)) * LAT + c] = S->z[r][c];
    }
    __syncthreads();
  }

  // ---- pose head (runs once; small share of total) ----
  for (int tix = 0; tix < TST; tix++) {
    for (int e = tid; e < RPB * LAT; e += TPB) {
      int r = e >> 8, c = e & 255;
      float v = g_traj[((row0 + r) * TST + tix) * LAT + c];
      S->a[r][c] = make_float2(v, v);
    }
    __syncthreads();

    layer_n512<true>(P1, pb1, &S->a[0][0], 264, &S->h1[0][0], 520, LAT, tid, S->sc);
    layer_n256<true, true>(P2, pb2, &S->h1[0][0], 520,
                           &S->h2[0][0], nullptr, 520, 512, tid, S->sc);

    // P3: 256 -> 128 (tiny), 128 threads, all rows
    if (tid < 128) {
      float acc[RPB];
      #pragma unroll
      for (int r = 0; r < RPB; r++) acc[r] = pb3[tid];
      #pragma unroll 4
      for (int k = 0; k < 256; k++) {
        float wv = P3[k * 128 + tid];
        #pragma unroll
        for (int r = 0; r < RPB; r++)
          acc[r] = fmaf(S->h2[r][k].x, wv, acc[r]);
      }
      #pragma unroll
      for (int r = 0; r < RPB; r++) {
        float v = fmaxf(acc[r], 0.0f);
        S->h1[r][tid] = make_float2(v, v);
      }
    }
    __syncthreads();

    if (tid < RPB * 7) {                   // final 128 -> 7
      int r = tid / 7, c = tid % 7;
      float acc = pb4[c];
      #pragma unroll 4
      for (int kk = 0; kk < 128; kk++)
        acc = fmaf(S->h1[r][kk].x, P4[kk * 7 + c], acc);
      S->z[r][c] = acc;
    }
    __syncthreads();

    if (tid < RPB) {
      int r = tid;
      float q0 = S->z[r][3], q1 = S->z[r][4], q2 = S->z[r][5], q3 = S->z[r][6];
      float nrm = sqrtf(q0*q0 + q1*q1 + q2*q2 + q3*q3);
      float dn  = fmaxf(nrm, 1e-12f);
      float* o = out + ((size_t)(row0 + r) * TST + tix) * 7;
      o[0] = S->z[r][0]; o[1] = S->z[r][1]; o[2] = S->z[r][2];
      o[3] = q0 / dn; o[4] = q1 / dn; o[5] = q2 / dn; o[6] = q3 / dn;
    }
    __syncthreads();
  }
}

// ---------------- launch ------------------------------------------------------
extern "C" void kernel_launch(void* const* d_in, const int* in_sizes, int n_in,
                              void* d_out, int out_size) {
  (void)in_sizes; (void)n_in; (void)out_size;
  const float* z0  = (const float*)d_in[0];
  const float* ts  = (const float*)d_in[1];
  const float* W1  = (const float*)d_in[2];
  const float* b1  = (const float*)d_in[3];
  const float* W2  = (const float*)d_in[4];
  const float* b2  = (const float*)d_in[5];
  const float* W3  = (const float*)d_in[6];
  const float* b3  = (const float*)d_in[7];
  const float* W4  = (const float*)d_in[8];
  const float* b4  = (const float*)d_in[9];
  const float* P1  = (const float*)d_in[10];
  const float* pb1 = (const float*)d_in[11];
  const float* P2  = (const float*)d_in[12];
  const float* pb2 = (const float*)d_in[13];
  const float* P3  = (const float*)d_in[14];
  const float* pb3 = (const float*)d_in[15];
  const float* P4  = (const float*)d_in[16];
  const float* pb4 = (const float*)d_in[17];
  float* out = (float*)d_out;

  cudaFuncSetAttribute(ode_kernel, cudaFuncAttributeMaxDynamicSharedMemorySize,
                       SMEM_BYTES);
  ode_kernel<<<NCTA, TPB, SMEM_BYTES>>>(z0, ts, W1, b1, W2, b2, W3, b3, W4, b4,
                                        P1, pb1, P2, pb2, P3, pb3, P4, pb4, out);
}